// round 6
// baseline (speedup 1.0000x reference)
#include <cuda_runtime.h>
#include <cuda_bf16.h>
#include <cstdint>

#define BB   1024
#define AN   256
#define DD   256
#define HD   512
#define AD   512
#define KIN  1024
#define NRR  400
#define NF2  656      // 256 live X2 cols + 400 relation cols
#define HUGEV 1e31f

// fp32 scratch
__device__ __align__(16) float g_X2h2[BB * DD];     // X2[:, 256:512]
__device__ __align__(16) float g_RP[BB * NRR];
__device__ __align__(16) float g_br[NRR];
// bf16 hi/lo planes
__device__ __align__(16) __nv_bfloat16 g_Ah [BB * KIN],  g_Al [BB * KIN];
__device__ __align__(16) __nv_bfloat16 g_W1h[KIN * AD],  g_W1l[KIN * AD];
__device__ __align__(16) __nv_bfloat16 g_W2h[AD * AD],   g_W2l[AD * AD];
__device__ __align__(16) __nv_bfloat16 g_Rh [NRR * DD],  g_Rl [NRR * DD];
__device__ __align__(16) __nv_bfloat16 g_Xh [BB * AD],   g_Xl [BB * AD];
__device__ __align__(16) __nv_bfloat16 g_Wrh[AD * NRR],  g_Wrl[AD * NRR];

// ---------------------------------------------------------------------------
__device__ __forceinline__ uint32_t sh_addr(const void* p) {
    return (uint32_t)__cvta_generic_to_shared(p);
}
__device__ __forceinline__ void cp16(uint32_t dst, const void* src, int sz) {
    asm volatile("cp.async.cg.shared.global [%0], [%1], 16, %2;" :: "r"(dst), "l"(src), "r"(sz));
}
__device__ __forceinline__ void cp_commit() { asm volatile("cp.async.commit_group;"); }
template<int N> __device__ __forceinline__ void cp_wait() {
    asm volatile("cp.async.wait_group %0;" :: "n"(N));
}
__device__ __forceinline__ void ldsm_x4(uint32_t& r0, uint32_t& r1, uint32_t& r2, uint32_t& r3, uint32_t a) {
    asm volatile("ldmatrix.sync.aligned.m8n8.x4.shared.b16 {%0,%1,%2,%3}, [%4];"
                 : "=r"(r0), "=r"(r1), "=r"(r2), "=r"(r3) : "r"(a));
}
__device__ __forceinline__ void ldsm_x4_t(uint32_t& r0, uint32_t& r1, uint32_t& r2, uint32_t& r3, uint32_t a) {
    asm volatile("ldmatrix.sync.aligned.m8n8.x4.trans.shared.b16 {%0,%1,%2,%3}, [%4];"
                 : "=r"(r0), "=r"(r1), "=r"(r2), "=r"(r3) : "r"(a));
}
__device__ __forceinline__ void mma16816(float c[4], const uint32_t a[4], const uint32_t b[2]) {
    asm volatile(
        "mma.sync.aligned.m16n8k16.row.col.f32.bf16.bf16.f32 "
        "{%0,%1,%2,%3}, {%4,%5,%6,%7}, {%8,%9}, {%0,%1,%2,%3};"
        : "+f"(c[0]), "+f"(c[1]), "+f"(c[2]), "+f"(c[3])
        : "r"(a[0]), "r"(a[1]), "r"(a[2]), "r"(a[3]), "r"(b[0]), "r"(b[1]));
}
__device__ __forceinline__ uint32_t pack2(__nv_bfloat16 a, __nv_bfloat16 b) {
    __nv_bfloat162 p = __halves2bfloat162(a, b);
    return *reinterpret_cast<uint32_t*>(&p);
}
__device__ __forceinline__ void split1(float x, __nv_bfloat16& h, __nv_bfloat16& l) {
    h = __float2bfloat16(x);
    l = __float2bfloat16(x - __bfloat162float(h));
}
__device__ __forceinline__ void split4(float4 v, uint2& hw, uint2& lw) {
    float xs[4] = {v.x, v.y, v.z, v.w};
    __nv_bfloat16 h[4], l[4];
    #pragma unroll
    for (int i = 0; i < 4; i++) split1(xs[i], h[i], l[i]);
    hw = {pack2(h[0], h[1]), pack2(h[2], h[3])};
    lw = {pack2(l[0], l[1]), pack2(l[2], l[3])};
}

// ---------------------------------------------------------------------------
// 32x64 tile, BK=32, 128 threads (4 warps: wm=w>>1 in [0,2) x 16 rows,
// wn=w&1 x 32 cols), 2-stage buffers.
// A plane [32][40].  B KN [32][72].  B NK [64][40].
// ---------------------------------------------------------------------------
#define MMA_TILE_KN(buf)                                                      \
    _Pragma("unroll")                                                         \
    for (int ks = 0; ks < 2; ks++) {                                          \
        uint32_t ah[4], al[4], bh[4][2], bl[4][2];                            \
        ldsm_x4(ah[0], ah[1], ah[2], ah[3], aAh[buf] + ks * 32);              \
        ldsm_x4(al[0], al[1], al[2], al[3], aAl[buf] + ks * 32);              \
        _Pragma("unroll")                                                     \
        for (int p = 0; p < 2; p++) {                                         \
            uint32_t off = (uint32_t)(ks * 16 * 144 + p * 32);                \
            ldsm_x4_t(bh[2*p][0], bh[2*p][1], bh[2*p+1][0], bh[2*p+1][1], aBh[buf] + off); \
            ldsm_x4_t(bl[2*p][0], bl[2*p][1], bl[2*p+1][0], bl[2*p+1][1], aBl[buf] + off); \
        }                                                                     \
        _Pragma("unroll")                                                     \
        for (int nt = 0; nt < 4; nt++) {                                      \
            mma16816(acc[nt], ah, bh[nt]);                                    \
            mma16816(acc[nt], ah, bl[nt]);                                    \
            mma16816(acc[nt], al, bh[nt]);                                    \
        }                                                                     \
    }

#define MMA_TILE_NK(buf)                                                      \
    _Pragma("unroll")                                                         \
    for (int ks = 0; ks < 2; ks++) {                                          \
        uint32_t ah[4], al[4], bh[4][2], bl[4][2];                            \
        ldsm_x4(ah[0], ah[1], ah[2], ah[3], aAh[buf] + ks * 32);              \
        ldsm_x4(al[0], al[1], al[2], al[3], aAl[buf] + ks * 32);              \
        _Pragma("unroll")                                                     \
        for (int p = 0; p < 2; p++) {                                         \
            uint32_t off = (uint32_t)(p * 16 * 80 + ks * 32);                 \
            ldsm_x4(bh[2*p][0], bh[2*p][1], bh[2*p+1][0], bh[2*p+1][1], aBh[buf] + off); \
            ldsm_x4(bl[2*p][0], bl[2*p][1], bl[2*p+1][0], bl[2*p+1][1], aBl[buf] + off); \
        }                                                                     \
        _Pragma("unroll")                                                     \
        for (int nt = 0; nt < 4; nt++) {                                      \
            mma16816(acc[nt], ah, bh[nt]);                                    \
            mma16816(acc[nt], ah, bl[nt]);                                    \
            mma16816(acc[nt], al, bh[nt]);                                    \
        }                                                                     \
    }

#define GEMM_IDS                                                              \
    int t = threadIdx.x;                                                      \
    int w = t >> 5, lane = t & 31;                                            \
    int wm = w >> 1, wn = w & 1;                                              \
    int gid = lane >> 2, tig = lane & 3;                                      \
    int lj = lane >> 3, lr = lane & 7;

#define LDSM_A_BASE(Ah, Al)                                                   \
    uint32_t aAh[2], aAl[2];                                                  \
    {   int a_row = wm * 16 + (lj & 1) * 8 + lr;                              \
        int a_kc  = (lj >> 1) * 8;                                            \
        _Pragma("unroll")                                                     \
        for (int s = 0; s < 2; s++) {                                         \
            aAh[s] = sh_addr(&Ah[s][a_row][a_kc]);                            \
            aAl[s] = sh_addr(&Al[s][a_row][a_kc]); } }

#define LDSM_BKN_BASE(Bh, Bl)                                                 \
    uint32_t aBh[2], aBl[2];                                                  \
    {   int b_kr = (lj & 1) * 8 + lr;                                         \
        int b_nc = wn * 32 + (lj >> 1) * 8;                                   \
        _Pragma("unroll")                                                     \
        for (int s = 0; s < 2; s++) {                                         \
            aBh[s] = sh_addr(&Bh[s][b_kr][b_nc]);                             \
            aBl[s] = sh_addr(&Bl[s][b_kr][b_nc]); } }

#define LDSM_BNK_BASE(Bh, Bl)                                                 \
    uint32_t aBh[2], aBl[2];                                                  \
    {   int b_nr = wn * 32 + (lj >> 1) * 8 + lr;                              \
        int b_kc = (lj & 1) * 8;                                              \
        _Pragma("unroll")                                                     \
        for (int s = 0; s < 2; s++) {                                         \
            aBh[s] = sh_addr(&Bh[s][b_nr][b_kc]);                             \
            aBl[s] = sh_addr(&Bl[s][b_nr][b_kc]); } }

// 2-stage pipeline: double sync per iter (writer must not touch the buffer
// other warps are still reading).
#define PIPE_LOOP2(NT, LOADER, MMA)                                           \
    LOADER(0, 0); cp_commit();                                                \
    int buf = 0;                                                              \
    for (int it = 0; it < NT; it++) {                                         \
        if (it + 1 < NT) { LOADER(it + 1, buf ^ 1); }                         \
        cp_commit();                                                          \
        cp_wait<1>();                                                         \
        __syncthreads();                                                      \
        MMA(buf);                                                             \
        __syncthreads();                                                      \
        buf ^= 1;                                                             \
    }

// ---------------------------------------------------------------------------
// k_prep: split W1/W2/rel into bf16 hi/lo planes; build gathered concat A.
// ---------------------------------------------------------------------------
#define U_A   (BB * KIN / 4)
#define U_W1  (KIN * AD / 4)
#define U_W2  (AD * AD / 4)
#define U_R   (NRR * DD / 4)
#define U_TOT (U_A + U_W1 + U_W2 + U_R)

__global__ void __launch_bounds__(256)
k_prep(const int* __restrict__ e, const int* __restrict__ q,
       const float* __restrict__ hstate,
       const float* __restrict__ ent_emb,
       const float* __restrict__ rel_emb,
       const float* __restrict__ W1, const float* __restrict__ W2)
{
    int u = blockIdx.x * 256 + threadIdx.x;
    if (u >= U_TOT) return;

    float4 v;
    __nv_bfloat16 *ph, *pl;
    size_t off;
    if (u < U_A) {
        int b  = u >> 8;
        int kc = (u & 255) * 4;
        const float* p = (kc < DD) ? ent_emb + (size_t)e[b] * DD + kc
                       : (kc < DD + HD) ? hstate + (size_t)b * HD + (kc - DD)
                       : rel_emb + (size_t)q[b] * DD + (kc - DD - HD);
        v = *(const float4*)p;
        off = (size_t)u * 4; ph = g_Ah; pl = g_Al;
    } else if (u < U_A + U_W1) {
        size_t i = (size_t)(u - U_A) * 4;
        v = *(const float4*)&W1[i];
        off = i; ph = g_W1h; pl = g_W1l;
    } else if (u < U_A + U_W1 + U_W2) {
        size_t i = (size_t)(u - U_A - U_W1) * 4;
        v = *(const float4*)&W2[i];
        off = i; ph = g_W2h; pl = g_W2l;
    } else {
        size_t i = (size_t)(u - U_A - U_W1 - U_W2) * 4;
        v = *(const float4*)&rel_emb[i];
        off = i; ph = g_Rh; pl = g_Rl;
    }
    uint2 hw, lw;
    split4(v, hw, lw);
    *(uint2*)&ph[off] = hw;
    *(uint2*)&pl[off] = lw;
}

// ---------------------------------------------------------------------------
// GEMM1: X = relu(A @ W1 + b1) -> bf16 hi/lo.  M=1024 K=1024 N=512.
// Tile 32x64, grid (8, 32).
// ---------------------------------------------------------------------------
__global__ void __launch_bounds__(128)
k_gemm1(const float* __restrict__ b1)
{
    __shared__ __nv_bfloat16 Ah[2][32][40], Al[2][32][40];
    __shared__ __nv_bfloat16 Bh[2][32][72], Bl[2][32][72];

    GEMM_IDS;
    int m0 = blockIdx.y * 32, n0 = blockIdx.x * 64;

    LDSM_A_BASE(Ah, Al);
    LDSM_BKN_BASE(Bh, Bl);

    int ar = t >> 2, ac = (t & 3) * 8;     // A: 32 rows x 32 k, 1 cp16/plane
    int br = t >> 3, bc = (t & 7) * 8;     // B: rows br, br+16, 2 cp16/plane
    const __nv_bfloat16* gAh = g_Ah + (size_t)(m0 + ar) * KIN + ac;
    const __nv_bfloat16* gAl = g_Al + (size_t)(m0 + ar) * KIN + ac;
    uint32_t dAh[2], dAl[2], dBh0[2], dBl0[2], dBh1[2], dBl1[2];
    #pragma unroll
    for (int s = 0; s < 2; s++) {
        dAh[s]  = sh_addr(&Ah[s][ar][ac]);      dAl[s]  = sh_addr(&Al[s][ar][ac]);
        dBh0[s] = sh_addr(&Bh[s][br][bc]);      dBl0[s] = sh_addr(&Bl[s][br][bc]);
        dBh1[s] = sh_addr(&Bh[s][br + 16][bc]); dBl1[s] = sh_addr(&Bl[s][br + 16][bc]);
    }

    float acc[4][4] = {};
    const int NT = KIN / 32;

    #define LOAD1(it, s) {                                                    \
        int k0 = (it) * 32;                                                   \
        cp16(dAh[s], gAh + k0, 16);                                           \
        cp16(dAl[s], gAl + k0, 16);                                           \
        cp16(dBh0[s], g_W1h + (size_t)(k0 + br) * AD + n0 + bc, 16);          \
        cp16(dBl0[s], g_W1l + (size_t)(k0 + br) * AD + n0 + bc, 16);          \
        cp16(dBh1[s], g_W1h + (size_t)(k0 + br + 16) * AD + n0 + bc, 16);     \
        cp16(dBl1[s], g_W1l + (size_t)(k0 + br + 16) * AD + n0 + bc, 16); }

    PIPE_LOOP2(NT, LOAD1, MMA_TILE_KN);
    #undef LOAD1

    #pragma unroll
    for (int nt = 0; nt < 4; nt++) {
        int r0 = m0 + wm * 16 + gid;
        int c0 = n0 + wn * 32 + nt * 8 + 2 * tig;
        float bb0 = b1[c0], bb1 = b1[c0 + 1];
        float v00 = fmaxf(acc[nt][0] + bb0, 0.f), v01 = fmaxf(acc[nt][1] + bb1, 0.f);
        float v10 = fmaxf(acc[nt][2] + bb0, 0.f), v11 = fmaxf(acc[nt][3] + bb1, 0.f);
        __nv_bfloat16 h0, l0, h1, l1;
        split1(v00, h0, l0); split1(v01, h1, l1);
        *(uint32_t*)&g_Xh[(size_t)r0 * AD + c0] = pack2(h0, h1);
        *(uint32_t*)&g_Xl[(size_t)r0 * AD + c0] = pack2(l0, l1);
        split1(v10, h0, l0); split1(v11, h1, l1);
        *(uint32_t*)&g_Xh[(size_t)(r0 + 8) * AD + c0] = pack2(h0, h1);
        *(uint32_t*)&g_Xl[(size_t)(r0 + 8) * AD + c0] = pack2(l0, l1);
    }
}

// ---------------------------------------------------------------------------
// Wr = W2[:, :256] @ rel_emb^T -> bf16 hi/lo.  M=512 N=400 K=256.
// Tile 32x64, grid (7, 16).
// ---------------------------------------------------------------------------
__global__ void __launch_bounds__(128)
k_wr()
{
    __shared__ __nv_bfloat16 Ah[2][32][40], Al[2][32][40];
    __shared__ __nv_bfloat16 Bh[2][64][40], Bl[2][64][40];

    GEMM_IDS;
    int m0 = blockIdx.y * 32, n0 = blockIdx.x * 64;

    LDSM_A_BASE(Ah, Al);
    LDSM_BNK_BASE(Bh, Bl);

    int ar = t >> 2, ac = (t & 3) * 8;
    int rr0 = n0 + ar, rr1 = n0 + ar + 32;
    int bsz0 = (rr0 < NRR) ? 16 : 0;
    int bsz1 = (rr1 < NRR) ? 16 : 0;
    const __nv_bfloat16* gRh0 = g_Rh + (size_t)(rr0 < NRR ? rr0 : 0) * DD + ac;
    const __nv_bfloat16* gRl0 = g_Rl + (size_t)(rr0 < NRR ? rr0 : 0) * DD + ac;
    const __nv_bfloat16* gRh1 = g_Rh + (size_t)(rr1 < NRR ? rr1 : 0) * DD + ac;
    const __nv_bfloat16* gRl1 = g_Rl + (size_t)(rr1 < NRR ? rr1 : 0) * DD + ac;
    uint32_t dAh[2], dAl[2], dBh0[2], dBl0[2], dBh1[2], dBl1[2];
    #pragma unroll
    for (int s = 0; s < 2; s++) {
        dAh[s]  = sh_addr(&Ah[s][ar][ac]);      dAl[s]  = sh_addr(&Al[s][ar][ac]);
        dBh0[s] = sh_addr(&Bh[s][ar][ac]);      dBl0[s] = sh_addr(&Bl[s][ar][ac]);
        dBh1[s] = sh_addr(&Bh[s][ar + 32][ac]); dBl1[s] = sh_addr(&Bl[s][ar + 32][ac]);
    }

    float acc[4][4] = {};
    const int NT = DD / 32;

    #define LOADW(it, s) {                                                    \
        int k0 = (it) * 32;                                                   \
        cp16(dAh[s], g_W2h + (size_t)(m0 + ar) * AD + k0 + ac, 16);           \
        cp16(dAl[s], g_W2l + (size_t)(m0 + ar) * AD + k0 + ac, 16);           \
        cp16(dBh0[s], gRh0 + k0, bsz0);                                       \
        cp16(dBl0[s], gRl0 + k0, bsz0);                                       \
        cp16(dBh1[s], gRh1 + k0, bsz1);                                       \
        cp16(dBl1[s], gRl1 + k0, bsz1); }

    PIPE_LOOP2(NT, LOADW, MMA_TILE_NK);
    #undef LOADW

    #pragma unroll
    for (int nt = 0; nt < 4; nt++) {
        int r0 = m0 + wm * 16 + gid;
        int c0 = n0 + wn * 32 + nt * 8 + 2 * tig;
        if (c0 < NRR) {
            __nv_bfloat16 h0, l0, h1, l1;
            split1(acc[nt][0], h0, l0); split1(acc[nt][1], h1, l1);
            *(uint32_t*)&g_Wrh[(size_t)r0 * NRR + c0] = pack2(h0, h1);
            *(uint32_t*)&g_Wrl[(size_t)r0 * NRR + c0] = pack2(l0, l1);
            split1(acc[nt][2], h0, l0); split1(acc[nt][3], h1, l1);
            *(uint32_t*)&g_Wrh[(size_t)(r0 + 8) * NRR + c0] = pack2(h0, h1);
            *(uint32_t*)&g_Wrl[(size_t)(r0 + 8) * NRR + c0] = pack2(l0, l1);
        }
    }
}

// br[r] = sum_j b2[j] * rel_emb[r*256+j]
__global__ void k_br(const float* __restrict__ b2, const float* __restrict__ rel_emb)
{
    int warp = threadIdx.x >> 5, lane = threadIdx.x & 31;
    int r = blockIdx.x * 8 + warp;
    if (r >= NRR) return;
    const float* rr = rel_emb + (size_t)r * DD;
    float s = 0.f;
    #pragma unroll
    for (int j = lane; j < DD; j += 32) s = fmaf(b2[j], rr[j], s);
    #pragma unroll
    for (int o = 16; o > 0; o >>= 1) s += __shfl_xor_sync(0xFFFFFFFFu, s, o);
    if (lane == 0) g_br[r] = s;
}

// ---------------------------------------------------------------------------
// GEMM2 (trimmed): [X2[:,256:512] | RP] = X @ [W2[:,256:512] | Wr] + bias.
// M=1024 K=512 N=656.  Tile 32x64, grid (11, 32).
// ---------------------------------------------------------------------------
__global__ void __launch_bounds__(128)
k_gemm2f(const float* __restrict__ b2)
{
    __shared__ __nv_bfloat16 Ah[2][32][40], Al[2][32][40];
    __shared__ __nv_bfloat16 Bh[2][32][72], Bl[2][32][72];

    GEMM_IDS;
    int m0 = blockIdx.y * 32, n0 = blockIdx.x * 64;

    LDSM_A_BASE(Ah, Al);
    LDSM_BKN_BASE(Bh, Bl);

    int ar = t >> 2, ac = (t & 3) * 8;
    int br = t >> 3, bc = (t & 7) * 8;
    int bcol = n0 + bc;
    const __nv_bfloat16* gAh = g_Xh + (size_t)(m0 + ar) * AD + ac;
    const __nv_bfloat16* gAl = g_Xl + (size_t)(m0 + ar) * AD + ac;
    uint32_t dAh[2], dAl[2], dBh0[2], dBl0[2], dBh1[2], dBl1[2];
    #pragma unroll
    for (int s = 0; s < 2; s++) {
        dAh[s]  = sh_addr(&Ah[s][ar][ac]);      dAl[s]  = sh_addr(&Al[s][ar][ac]);
        dBh0[s] = sh_addr(&Bh[s][br][bc]);      dBl0[s] = sh_addr(&Bl[s][br][bc]);
        dBh1[s] = sh_addr(&Bh[s][br + 16][bc]); dBl1[s] = sh_addr(&Bl[s][br + 16][bc]);
    }

    float acc[4][4] = {};
    const int NT = AD / 32;

    #define LOAD2(it, s) {                                                    \
        int k0 = (it) * 32;                                                   \
        cp16(dAh[s], gAh + k0, 16);                                           \
        cp16(dAl[s], gAl + k0, 16);                                           \
        _Pragma("unroll")                                                     \
        for (int hh = 0; hh < 2; hh++) {                                      \
            int kk = k0 + br + hh * 16;                                       \
            const __nv_bfloat16 *sh_, *sl_; int sz_ = 16;                     \
            if (bcol < DD)       { sh_ = g_W2h + (size_t)kk * AD + DD + bcol; \
                                   sl_ = g_W2l + (size_t)kk * AD + DD + bcol; }\
            else if (bcol < NF2) { sh_ = g_Wrh + (size_t)kk * NRR + (bcol - DD);\
                                   sl_ = g_Wrl + (size_t)kk * NRR + (bcol - DD); }\
            else                 { sh_ = g_W2h; sl_ = g_W2l; sz_ = 0; }       \
            cp16(hh ? dBh1[s] : dBh0[s], sh_, sz_);                           \
            cp16(hh ? dBl1[s] : dBl0[s], sl_, sz_);                           \
        } }

    PIPE_LOOP2(NT, LOAD2, MMA_TILE_KN);
    #undef LOAD2

    #pragma unroll
    for (int nt = 0; nt < 4; nt++) {
        int r0 = m0 + wm * 16 + gid;
        int c0 = n0 + wn * 32 + nt * 8 + 2 * tig;
        if (c0 < DD) {
            float bb0 = b2[DD + c0], bb1 = b2[DD + c0 + 1];
            float2 v0 = {acc[nt][0] + bb0, acc[nt][1] + bb1};
            float2 v1 = {acc[nt][2] + bb0, acc[nt][3] + bb1};
            *(float2*)&g_X2h2[(size_t)r0 * DD + c0]       = v0;
            *(float2*)&g_X2h2[(size_t)(r0 + 8) * DD + c0] = v1;
        } else if (c0 < NF2) {
            int rel = c0 - DD;
            float bb0 = g_br[rel], bb1 = g_br[rel + 1];
            float2 v0 = {acc[nt][0] + bb0, acc[nt][1] + bb1};
            float2 v1 = {acc[nt][2] + bb0, acc[nt][3] + bb1};
            *(float2*)&g_RP[(size_t)r0 * NRR + rel]       = v0;
            *(float2*)&g_RP[(size_t)(r0 + 8) * NRR + rel] = v1;
        }
    }
}

// ---------------------------------------------------------------------------
// Scores + masked softmax + entropy.
// ---------------------------------------------------------------------------
__global__ void k_scores(const int*   __restrict__ r_space,
                         const int*   __restrict__ e_space,
                         const float* __restrict__ mask,
                         const float* __restrict__ ent_emb,
                         float* __restrict__ dist,
                         float* __restrict__ entropy)
{
    int b = blockIdx.x;
    int t = threadIdx.x;
    int warp = t >> 5, lane = t & 31;

    __shared__ __align__(16) float x2b[DD];
    __shared__ float rp[NRR];
    __shared__ float sc[AN];
    __shared__ float red[8];

    x2b[t] = g_X2h2[(size_t)b * DD + t];
    for (int i = t; i < NRR; i += 256) rp[i] = g_RP[(size_t)b * NRR + i];
    __syncthreads();

    const float4* xp = reinterpret_cast<const float4*>(x2b);
    float4 xv0 = xp[lane * 2 + 0];
    float4 xv1 = xp[lane * 2 + 1];

    const int base = b * AN;
    for (int a0 = warp * 8; a0 < AN; a0 += 64) {
        int idx[8];
        #pragma unroll
        for (int j = 0; j < 8; j++) idx[j] = e_space[base + a0 + j];
        float4 v0[8], v1[8];
        #pragma unroll
        for (int j = 0; j < 8; j++) {
            const float4* ep = reinterpret_cast<const float4*>(ent_emb + (size_t)idx[j] * DD);
            v0[j] = ep[lane * 2 + 0];
            v1[j] = ep[lane * 2 + 1];
        }
        float s[8];
        #pragma unroll
        for (int j = 0; j < 8; j++) {
            s[j] = v0[j].x * xv0.x + v0[j].y * xv0.y + v0[j].z * xv0.z + v0[j].w * xv0.w
                 + v1[j].x * xv1.x + v1[j].y * xv1.y + v1[j].z * xv1.z + v1[j].w * xv1.w;
        }
        #pragma unroll
        for (int o = 16; o > 0; o >>= 1) {
            #pragma unroll
            for (int j = 0; j < 8; j++) s[j] += __shfl_xor_sync(0xFFFFFFFFu, s[j], o);
        }
        if (lane < 8) {
            int a = a0 + lane;
            int ir = r_space[base + a];
            float m = mask[base + a];
            sc[a] = s[lane] + rp[ir] - (1.0f - m) * HUGEV;
        }
    }
    __syncthreads();

    float s = sc[t];

    float mx = s;
    #pragma unroll
    for (int o = 16; o > 0; o >>= 1) mx = fmaxf(mx, __shfl_xor_sync(0xFFFFFFFFu, mx, o));
    if (lane == 0) red[warp] = mx;
    __syncthreads();
    if (t < 8) {
        float v = red[t];
        #pragma unroll
        for (int o = 4; o > 0; o >>= 1) v = fmaxf(v, __shfl_xor_sync(0xFFu, v, o));
        if (t == 0) red[0] = v;
    }
    __syncthreads();
    mx = red[0];

    float ex = expf(s - mx);

    float sm = ex;
    #pragma unroll
    for (int o = 16; o > 0; o >>= 1) sm += __shfl_xor_sync(0xFFFFFFFFu, sm, o);
    __syncthreads();
    if (lane == 0) red[warp] = sm;
    __syncthreads();
    if (t < 8) {
        float v = red[t];
        #pragma unroll
        for (int o = 4; o > 0; o >>= 1) v += __shfl_xor_sync(0xFFu, v, o);
        if (t == 0) red[0] = v;
    }
    __syncthreads();
    float total = red[0];

    float p = ex / total;
    dist[(size_t)b * AN + t] = p;

    float term = p * logf(fmaxf(p, 1e-20f));
    float es = term;
    #pragma unroll
    for (int o = 16; o > 0; o >>= 1) es += __shfl_xor_sync(0xFFFFFFFFu, es, o);
    __syncthreads();
    if (lane == 0) red[warp] = es;
    __syncthreads();
    if (t < 8) {
        float v = red[t];
        #pragma unroll
        for (int o = 4; o > 0; o >>= 1) v += __shfl_xor_sync(0xFFu, v, o);
        if (t == 0) entropy[b] = -v;
    }
}

// ---------------------------------------------------------------------------
extern "C" void kernel_launch(void* const* d_in, const int* in_sizes, int n_in,
                              void* d_out, int out_size)
{
    const int*   e        = (const int*)  d_in[0];
    const int*   q        = (const int*)  d_in[1];
    const float* hstate   = (const float*)d_in[2];
    const int*   r_space  = (const int*)  d_in[3];
    const int*   e_space  = (const int*)  d_in[4];
    const float* amask    = (const float*)d_in[5];
    const float* ent_emb  = (const float*)d_in[6];
    const float* rel_emb  = (const float*)d_in[7];
    const float* W1       = (const float*)d_in[8];
    const float* b1       = (const float*)d_in[9];
    const float* W2       = (const float*)d_in[10];
    const float* b2       = (const float*)d_in[11];

    float* dist    = (float*)d_out;
    float* entropy = (float*)d_out + (size_t)BB * AN;

    k_prep<<<(U_TOT + 255) / 256, 256>>>(e, q, hstate, ent_emb, rel_emb, W1, W2);
    k_br<<<(NRR + 7) / 8, 256>>>(b2, rel_emb);

    dim3 gw((NRR + 63) / 64, AD / 32);          // (7, 16) = 112
    k_wr<<<gw, 128>>>();

    dim3 g1(AD / 64, BB / 32);                  // (8, 32) = 256
    k_gemm1<<<g1, 128>>>(b1);

    dim3 g2((NF2 + 63) / 64, BB / 32);          // (11, 32) = 352
    k_gemm2f<<<g2, 128>>>(b2);

    k_scores<<<BB, 256>>>(r_space, e_space, amask, ent_emb, dist, entropy);
}

// round 7
// speedup vs baseline: 1.0264x; 1.0264x over previous
#include <cuda_runtime.h>
#include <cuda_bf16.h>
#include <cstdint>

#define BB   1024
#define AN   256
#define DD   256
#define HD   512
#define AD   512
#define KIN  1024
#define NRR  400
#define NF2  656      // 256 live X2 cols + 400 relation cols
#define HUGEV 1e31f

// fp32 scratch
__device__ __align__(16) float g_P0[BB * AD],  g_P1[BB * AD];    // gemm1 split-K partials
__device__ __align__(16) float g_Q0[BB * NF2], g_Q1[BB * NF2];   // gemm2f split-K partials
__device__ __align__(16) float g_br[NRR];
// bf16 hi/lo planes
__device__ __align__(16) __nv_bfloat16 g_Ah [BB * KIN],  g_Al [BB * KIN];
__device__ __align__(16) __nv_bfloat16 g_W1h[KIN * AD],  g_W1l[KIN * AD];
__device__ __align__(16) __nv_bfloat16 g_W2h[AD * AD],   g_W2l[AD * AD];
__device__ __align__(16) __nv_bfloat16 g_Rh [NRR * DD],  g_Rl [NRR * DD];
__device__ __align__(16) __nv_bfloat16 g_Xh [BB * AD],   g_Xl [BB * AD];
__device__ __align__(16) __nv_bfloat16 g_Wrh[AD * NRR],  g_Wrl[AD * NRR];

// ---------------------------------------------------------------------------
__device__ __forceinline__ uint32_t sh_addr(const void* p) {
    return (uint32_t)__cvta_generic_to_shared(p);
}
__device__ __forceinline__ void cp16(uint32_t dst, const void* src, int sz) {
    asm volatile("cp.async.cg.shared.global [%0], [%1], 16, %2;" :: "r"(dst), "l"(src), "r"(sz));
}
__device__ __forceinline__ void cp_commit() { asm volatile("cp.async.commit_group;"); }
template<int N> __device__ __forceinline__ void cp_wait() {
    asm volatile("cp.async.wait_group %0;" :: "n"(N));
}
__device__ __forceinline__ void ldsm_x4(uint32_t& r0, uint32_t& r1, uint32_t& r2, uint32_t& r3, uint32_t a) {
    asm volatile("ldmatrix.sync.aligned.m8n8.x4.shared.b16 {%0,%1,%2,%3}, [%4];"
                 : "=r"(r0), "=r"(r1), "=r"(r2), "=r"(r3) : "r"(a));
}
__device__ __forceinline__ void ldsm_x4_t(uint32_t& r0, uint32_t& r1, uint32_t& r2, uint32_t& r3, uint32_t a) {
    asm volatile("ldmatrix.sync.aligned.m8n8.x4.trans.shared.b16 {%0,%1,%2,%3}, [%4];"
                 : "=r"(r0), "=r"(r1), "=r"(r2), "=r"(r3) : "r"(a));
}
__device__ __forceinline__ void mma16816(float c[4], const uint32_t a[4], const uint32_t b[2]) {
    asm volatile(
        "mma.sync.aligned.m16n8k16.row.col.f32.bf16.bf16.f32 "
        "{%0,%1,%2,%3}, {%4,%5,%6,%7}, {%8,%9}, {%0,%1,%2,%3};"
        : "+f"(c[0]), "+f"(c[1]), "+f"(c[2]), "+f"(c[3])
        : "r"(a[0]), "r"(a[1]), "r"(a[2]), "r"(a[3]), "r"(b[0]), "r"(b[1]));
}
__device__ __forceinline__ uint32_t pack2(__nv_bfloat16 a, __nv_bfloat16 b) {
    __nv_bfloat162 p = __halves2bfloat162(a, b);
    return *reinterpret_cast<uint32_t*>(&p);
}
__device__ __forceinline__ void split1(float x, __nv_bfloat16& h, __nv_bfloat16& l) {
    h = __float2bfloat16(x);
    l = __float2bfloat16(x - __bfloat162float(h));
}
__device__ __forceinline__ void split4(float4 v, uint2& hw, uint2& lw) {
    float xs[4] = {v.x, v.y, v.z, v.w};
    __nv_bfloat16 h[4], l[4];
    #pragma unroll
    for (int i = 0; i < 4; i++) split1(xs[i], h[i], l[i]);
    hw = {pack2(h[0], h[1]), pack2(h[2], h[3])};
    lw = {pack2(l[0], l[1]), pack2(l[2], l[3])};
}

// ---------------------------------------------------------------------------
// 64x64 tile, BK=32, 256 threads (8 warps: wm in [0,4) x 16 rows, wn in
// [0,2) x 32 cols), 3-stage buffers (round-5 measured-best geometry).
// A plane [64][40], B KN [32][72], B NK [64][40].
// ---------------------------------------------------------------------------
#define MMA_TILE_KN(buf)                                                      \
    _Pragma("unroll")                                                         \
    for (int ks = 0; ks < 2; ks++) {                                          \
        uint32_t ah[4], al[4], bh[4][2], bl[4][2];                            \
        ldsm_x4(ah[0], ah[1], ah[2], ah[3], aAh[buf] + ks * 32);              \
        ldsm_x4(al[0], al[1], al[2], al[3], aAl[buf] + ks * 32);              \
        _Pragma("unroll")                                                     \
        for (int p = 0; p < 2; p++) {                                         \
            uint32_t off = (uint32_t)(ks * 16 * 144 + p * 32);                \
            ldsm_x4_t(bh[2*p][0], bh[2*p][1], bh[2*p+1][0], bh[2*p+1][1], aBh[buf] + off); \
            ldsm_x4_t(bl[2*p][0], bl[2*p][1], bl[2*p+1][0], bl[2*p+1][1], aBl[buf] + off); \
        }                                                                     \
        _Pragma("unroll")                                                     \
        for (int nt = 0; nt < 4; nt++) {                                      \
            mma16816(acc[nt], ah, bh[nt]);                                    \
            mma16816(acc[nt], ah, bl[nt]);                                    \
            mma16816(acc[nt], al, bh[nt]);                                    \
        }                                                                     \
    }

#define MMA_TILE_NK(buf)                                                      \
    _Pragma("unroll")                                                         \
    for (int ks = 0; ks < 2; ks++) {                                          \
        uint32_t ah[4], al[4], bh[4][2], bl[4][2];                            \
        ldsm_x4(ah[0], ah[1], ah[2], ah[3], aAh[buf] + ks * 32);              \
        ldsm_x4(al[0], al[1], al[2], al[3], aAl[buf] + ks * 32);              \
        _Pragma("unroll")                                                     \
        for (int p = 0; p < 2; p++) {                                         \
            uint32_t off = (uint32_t)(p * 16 * 80 + ks * 32);                 \
            ldsm_x4(bh[2*p][0], bh[2*p][1], bh[2*p+1][0], bh[2*p+1][1], aBh[buf] + off); \
            ldsm_x4(bl[2*p][0], bl[2*p][1], bl[2*p+1][0], bl[2*p+1][1], aBl[buf] + off); \
        }                                                                     \
        _Pragma("unroll")                                                     \
        for (int nt = 0; nt < 4; nt++) {                                      \
            mma16816(acc[nt], ah, bh[nt]);                                    \
            mma16816(acc[nt], ah, bl[nt]);                                    \
            mma16816(acc[nt], al, bh[nt]);                                    \
        }                                                                     \
    }

#define GEMM_IDS                                                              \
    int t = threadIdx.x;                                                      \
    int w = t >> 5, lane = t & 31;                                            \
    int wm = w >> 1, wn = w & 1;                                              \
    int gid = lane >> 2, tig = lane & 3;                                      \
    int lj = lane >> 3, lr = lane & 7;

#define LDSM_A_BASE(Ah, Al)                                                   \
    uint32_t aAh[3], aAl[3];                                                  \
    {   int a_row = wm * 16 + (lj & 1) * 8 + lr;                              \
        int a_kc  = (lj >> 1) * 8;                                            \
        _Pragma("unroll")                                                     \
        for (int s = 0; s < 3; s++) {                                         \
            aAh[s] = sh_addr(&Ah[s][a_row][a_kc]);                            \
            aAl[s] = sh_addr(&Al[s][a_row][a_kc]); } }

#define LDSM_BKN_BASE(Bh, Bl)                                                 \
    uint32_t aBh[3], aBl[3];                                                  \
    {   int b_kr = (lj & 1) * 8 + lr;                                         \
        int b_nc = wn * 32 + (lj >> 1) * 8;                                   \
        _Pragma("unroll")                                                     \
        for (int s = 0; s < 3; s++) {                                         \
            aBh[s] = sh_addr(&Bh[s][b_kr][b_nc]);                             \
            aBl[s] = sh_addr(&Bl[s][b_kr][b_nc]); } }

#define LDSM_BNK_BASE(Bh, Bl)                                                 \
    uint32_t aBh[3], aBl[3];                                                  \
    {   int b_nr = wn * 32 + (lj >> 1) * 8 + lr;                              \
        int b_kc = (lj & 1) * 8;                                              \
        _Pragma("unroll")                                                     \
        for (int s = 0; s < 3; s++) {                                         \
            aBh[s] = sh_addr(&Bh[s][b_nr][b_kc]);                             \
            aBl[s] = sh_addr(&Bl[s][b_nr][b_kc]); } }

// 3-stage pipeline (round-5): single sync per iter; the stage loaded at iter
// it is (it+2)%3, which all warps finished reading at iter it-1 (guarded by
// this iteration's __syncthreads).
#define PIPE_LOOP(NT, LOADER, MMA)                                            \
    LOADER(0, 0); cp_commit();                                                \
    LOADER(1, 1); cp_commit();                                                \
    int buf = 0;                                                              \
    for (int it = 0; it < NT; it++) {                                         \
        cp_wait<1>();                                                         \
        __syncthreads();                                                      \
        if (it + 2 < NT) { LOADER(it + 2, (it + 2) % 3); }                    \
        cp_commit();                                                          \
        MMA(buf);                                                             \
        buf = (buf + 1) % 3;                                                  \
    }

// ---------------------------------------------------------------------------
// k_prep: split W1/W2/rel into bf16 hi/lo planes; build gathered concat A.
// ---------------------------------------------------------------------------
#define U_A   (BB * KIN / 4)
#define U_W1  (KIN * AD / 4)
#define U_W2  (AD * AD / 4)
#define U_R   (NRR * DD / 4)
#define U_TOT (U_A + U_W1 + U_W2 + U_R)

__global__ void __launch_bounds__(256)
k_prep(const int* __restrict__ e, const int* __restrict__ q,
       const float* __restrict__ hstate,
       const float* __restrict__ ent_emb,
       const float* __restrict__ rel_emb,
       const float* __restrict__ W1, const float* __restrict__ W2)
{
    int u = blockIdx.x * 256 + threadIdx.x;
    if (u >= U_TOT) return;

    float4 v;
    __nv_bfloat16 *ph, *pl;
    size_t off;
    if (u < U_A) {
        int b  = u >> 8;
        int kc = (u & 255) * 4;
        const float* p = (kc < DD) ? ent_emb + (size_t)e[b] * DD + kc
                       : (kc < DD + HD) ? hstate + (size_t)b * HD + (kc - DD)
                       : rel_emb + (size_t)q[b] * DD + (kc - DD - HD);
        v = *(const float4*)p;
        off = (size_t)u * 4; ph = g_Ah; pl = g_Al;
    } else if (u < U_A + U_W1) {
        size_t i = (size_t)(u - U_A) * 4;
        v = *(const float4*)&W1[i];
        off = i; ph = g_W1h; pl = g_W1l;
    } else if (u < U_A + U_W1 + U_W2) {
        size_t i = (size_t)(u - U_A - U_W1) * 4;
        v = *(const float4*)&W2[i];
        off = i; ph = g_W2h; pl = g_W2l;
    } else {
        size_t i = (size_t)(u - U_A - U_W1 - U_W2) * 4;
        v = *(const float4*)&rel_emb[i];
        off = i; ph = g_Rh; pl = g_Rl;
    }
    uint2 hw, lw;
    split4(v, hw, lw);
    *(uint2*)&ph[off] = hw;
    *(uint2*)&pl[off] = lw;
}

// ---------------------------------------------------------------------------
// GEMM1 split-K: P[z] = A[:, z*512:(z+1)*512] @ W1[z*512:(z+1)*512, :].
// M=1024 Khalf=512 N=512.  Grid (8, 16, 2).
// ---------------------------------------------------------------------------
__global__ void __launch_bounds__(256)
k_gemm1()
{
    __shared__ __nv_bfloat16 Ah[3][64][40], Al[3][64][40];
    __shared__ __nv_bfloat16 Bh[3][32][72], Bl[3][32][72];

    GEMM_IDS;
    int m0 = blockIdx.y * 64, n0 = blockIdx.x * 64;
    int koff = blockIdx.z * (KIN / 2);
    float* P = blockIdx.z ? g_P1 : g_P0;

    LDSM_A_BASE(Ah, Al);
    LDSM_BKN_BASE(Bh, Bl);

    int ar = t >> 2, ac = (t & 3) * 8;
    int br = t >> 3, bc = (t & 7) * 8;
    const __nv_bfloat16* gAh = g_Ah + (size_t)(m0 + ar) * KIN + koff + ac;
    const __nv_bfloat16* gAl = g_Al + (size_t)(m0 + ar) * KIN + koff + ac;
    uint32_t dAh[3], dAl[3], dBh[3], dBl[3];
    #pragma unroll
    for (int s = 0; s < 3; s++) {
        dAh[s] = sh_addr(&Ah[s][ar][ac]); dAl[s] = sh_addr(&Al[s][ar][ac]);
        dBh[s] = sh_addr(&Bh[s][br][bc]); dBl[s] = sh_addr(&Bl[s][br][bc]);
    }

    float acc[4][4] = {};
    const int NT = (KIN / 2) / 32;

    #define LOAD1(it, s) {                                                    \
        int k0 = (it) * 32;                                                   \
        cp16(dAh[s], gAh + k0, 16);                                           \
        cp16(dAl[s], gAl + k0, 16);                                           \
        cp16(dBh[s], g_W1h + (size_t)(koff + k0 + br) * AD + n0 + bc, 16);    \
        cp16(dBl[s], g_W1l + (size_t)(koff + k0 + br) * AD + n0 + bc, 16); }

    PIPE_LOOP(NT, LOAD1, MMA_TILE_KN);
    #undef LOAD1

    #pragma unroll
    for (int nt = 0; nt < 4; nt++) {
        int r0 = m0 + wm * 16 + gid;
        int c0 = n0 + wn * 32 + nt * 8 + 2 * tig;
        *(float2*)&P[(size_t)r0 * AD + c0]       = {acc[nt][0], acc[nt][1]};
        *(float2*)&P[(size_t)(r0 + 8) * AD + c0] = {acc[nt][2], acc[nt][3]};
    }
}

// ---------------------------------------------------------------------------
// k_comb1: X = relu(P0 + P1 + b1) -> bf16 hi/lo planes.
// ---------------------------------------------------------------------------
__global__ void __launch_bounds__(256)
k_comb1(const float* __restrict__ b1)
{
    int u = blockIdx.x * 256 + threadIdx.x;       // float4 units over BB*AD
    size_t off = (size_t)u * 4;
    int c = off & (AD - 1);
    float4 p0 = *(const float4*)&g_P0[off];
    float4 p1 = *(const float4*)&g_P1[off];
    float4 bb = *(const float4*)&b1[c];
    float4 v = {fmaxf(p0.x + p1.x + bb.x, 0.f), fmaxf(p0.y + p1.y + bb.y, 0.f),
                fmaxf(p0.z + p1.z + bb.z, 0.f), fmaxf(p0.w + p1.w + bb.w, 0.f)};
    uint2 hw, lw;
    split4(v, hw, lw);
    *(uint2*)&g_Xh[off] = hw;
    *(uint2*)&g_Xl[off] = lw;
}

// ---------------------------------------------------------------------------
// Wr = W2[:, :256] @ rel_emb^T -> bf16 hi/lo.  M=512 N=400 K=256.
// ---------------------------------------------------------------------------
__global__ void __launch_bounds__(256)
k_wr()
{
    __shared__ __nv_bfloat16 Ah[3][64][40], Al[3][64][40];
    __shared__ __nv_bfloat16 Bh[3][64][40], Bl[3][64][40];

    GEMM_IDS;
    int m0 = blockIdx.y * 64, n0 = blockIdx.x * 64;

    LDSM_A_BASE(Ah, Al);
    LDSM_BNK_BASE(Bh, Bl);

    int ar = t >> 2, ac = (t & 3) * 8;
    int rr = n0 + ar;
    int bsz = (rr < NRR) ? 16 : 0;
    const __nv_bfloat16* gRh = g_Rh + (size_t)(rr < NRR ? rr : 0) * DD + ac;
    const __nv_bfloat16* gRl = g_Rl + (size_t)(rr < NRR ? rr : 0) * DD + ac;
    uint32_t dAh[3], dAl[3], dBh[3], dBl[3];
    #pragma unroll
    for (int s = 0; s < 3; s++) {
        dAh[s] = sh_addr(&Ah[s][ar][ac]); dAl[s] = sh_addr(&Al[s][ar][ac]);
        dBh[s] = sh_addr(&Bh[s][ar][ac]); dBl[s] = sh_addr(&Bl[s][ar][ac]);
    }

    float acc[4][4] = {};
    const int NT = DD / 32;

    #define LOADW(it, s) {                                                    \
        int k0 = (it) * 32;                                                   \
        cp16(dAh[s], g_W2h + (size_t)(m0 + ar) * AD + k0 + ac, 16);           \
        cp16(dAl[s], g_W2l + (size_t)(m0 + ar) * AD + k0 + ac, 16);           \
        cp16(dBh[s], gRh + k0, bsz);                                          \
        cp16(dBl[s], gRl + k0, bsz); }

    PIPE_LOOP(NT, LOADW, MMA_TILE_NK);
    #undef LOADW

    #pragma unroll
    for (int nt = 0; nt < 4; nt++) {
        int r0 = m0 + wm * 16 + gid;
        int c0 = n0 + wn * 32 + nt * 8 + 2 * tig;
        if (c0 < NRR) {
            __nv_bfloat16 h0, l0, h1, l1;
            split1(acc[nt][0], h0, l0); split1(acc[nt][1], h1, l1);
            *(uint32_t*)&g_Wrh[(size_t)r0 * NRR + c0] = pack2(h0, h1);
            *(uint32_t*)&g_Wrl[(size_t)r0 * NRR + c0] = pack2(l0, l1);
            split1(acc[nt][2], h0, l0); split1(acc[nt][3], h1, l1);
            *(uint32_t*)&g_Wrh[(size_t)(r0 + 8) * NRR + c0] = pack2(h0, h1);
            *(uint32_t*)&g_Wrl[(size_t)(r0 + 8) * NRR + c0] = pack2(l0, l1);
        }
    }
}

// br[r] = sum_j b2[j] * rel_emb[r*256+j]
__global__ void k_br(const float* __restrict__ b2, const float* __restrict__ rel_emb)
{
    int warp = threadIdx.x >> 5, lane = threadIdx.x & 31;
    int r = blockIdx.x * 8 + warp;
    if (r >= NRR) return;
    const float* rr = rel_emb + (size_t)r * DD;
    float s = 0.f;
    #pragma unroll
    for (int j = lane; j < DD; j += 32) s = fmaf(b2[j], rr[j], s);
    #pragma unroll
    for (int o = 16; o > 0; o >>= 1) s += __shfl_xor_sync(0xFFFFFFFFu, s, o);
    if (lane == 0) g_br[r] = s;
}

// ---------------------------------------------------------------------------
// GEMM2 split-K: Q[z] = X[:, z*256:(z+1)*256] @ Bcat[z*256:(z+1)*256, :].
// Bcat = [W2[:,256:512] | Wr].  M=1024 Khalf=256 N=656.  Grid (11, 16, 2).
// Bias deferred to k_scores.
// ---------------------------------------------------------------------------
__global__ void __launch_bounds__(256)
k_gemm2f()
{
    __shared__ __nv_bfloat16 Ah[3][64][40], Al[3][64][40];
    __shared__ __nv_bfloat16 Bh[3][32][72], Bl[3][32][72];

    GEMM_IDS;
    int m0 = blockIdx.y * 64, n0 = blockIdx.x * 64;
    int koff = blockIdx.z * (AD / 2);
    float* Q = blockIdx.z ? g_Q1 : g_Q0;

    LDSM_A_BASE(Ah, Al);
    LDSM_BKN_BASE(Bh, Bl);

    int ar = t >> 2, ac = (t & 3) * 8;
    int br = t >> 3, bc = (t & 7) * 8;
    int bcol = n0 + bc;
    const __nv_bfloat16* gAh = g_Xh + (size_t)(m0 + ar) * AD + koff + ac;
    const __nv_bfloat16* gAl = g_Xl + (size_t)(m0 + ar) * AD + koff + ac;
    uint32_t dAh[3], dAl[3], dBh[3], dBl[3];
    #pragma unroll
    for (int s = 0; s < 3; s++) {
        dAh[s] = sh_addr(&Ah[s][ar][ac]); dAl[s] = sh_addr(&Al[s][ar][ac]);
        dBh[s] = sh_addr(&Bh[s][br][bc]); dBl[s] = sh_addr(&Bl[s][br][bc]);
    }

    float acc[4][4] = {};
    const int NT = (AD / 2) / 32;

    #define LOAD2(it, s) {                                                    \
        int k0 = (it) * 32;                                                   \
        cp16(dAh[s], gAh + k0, 16);                                           \
        cp16(dAl[s], gAl + k0, 16);                                           \
        int kk = koff + k0 + br;                                              \
        const __nv_bfloat16 *sh_, *sl_; int sz_ = 16;                         \
        if (bcol < DD)       { sh_ = g_W2h + (size_t)kk * AD + DD + bcol;     \
                               sl_ = g_W2l + (size_t)kk * AD + DD + bcol; }   \
        else if (bcol < NF2) { sh_ = g_Wrh + (size_t)kk * NRR + (bcol - DD);  \
                               sl_ = g_Wrl + (size_t)kk * NRR + (bcol - DD); }\
        else                 { sh_ = g_W2h; sl_ = g_W2l; sz_ = 0; }           \
        cp16(dBh[s], sh_, sz_);                                               \
        cp16(dBl[s], sl_, sz_); }

    PIPE_LOOP(NT, LOAD2, MMA_TILE_KN);
    #undef LOAD2

    #pragma unroll
    for (int nt = 0; nt < 4; nt++) {
        int r0 = m0 + wm * 16 + gid;
        int c0 = n0 + wn * 32 + nt * 8 + 2 * tig;
        if (c0 < NF2) {   // c0 even, so c0+1 < NF2 too
            *(float2*)&Q[(size_t)r0 * NF2 + c0]       = {acc[nt][0], acc[nt][1]};
            *(float2*)&Q[(size_t)(r0 + 8) * NF2 + c0] = {acc[nt][2], acc[nt][3]};
        }
    }
}

// ---------------------------------------------------------------------------
// Scores + masked softmax + entropy. Combines the gemm2f split-K partials
// (plus bias) during smem staging.
// ---------------------------------------------------------------------------
__global__ void k_scores(const int*   __restrict__ r_space,
                         const int*   __restrict__ e_space,
                         const float* __restrict__ mask,
                         const float* __restrict__ ent_emb,
                         const float* __restrict__ b2,
                         float* __restrict__ dist,
                         float* __restrict__ entropy)
{
    int b = blockIdx.x;
    int t = threadIdx.x;
    int warp = t >> 5, lane = t & 31;

    __shared__ __align__(16) float x2b[DD];
    __shared__ float rp[NRR];
    __shared__ float sc[AN];
    __shared__ float red[8];

    const size_t qb = (size_t)b * NF2;
    x2b[t] = g_Q0[qb + t] + g_Q1[qb + t] + b2[DD + t];
    for (int i = t; i < NRR; i += 256)
        rp[i] = g_Q0[qb + DD + i] + g_Q1[qb + DD + i] + g_br[i];
    __syncthreads();

    const float4* xp = reinterpret_cast<const float4*>(x2b);
    float4 xv0 = xp[lane * 2 + 0];
    float4 xv1 = xp[lane * 2 + 1];

    const int base = b * AN;
    for (int a0 = warp * 8; a0 < AN; a0 += 64) {
        int idx[8];
        #pragma unroll
        for (int j = 0; j < 8; j++) idx[j] = e_space[base + a0 + j];
        float4 v0[8], v1[8];
        #pragma unroll
        for (int j = 0; j < 8; j++) {
            const float4* ep = reinterpret_cast<const float4*>(ent_emb + (size_t)idx[j] * DD);
            v0[j] = ep[lane * 2 + 0];
            v1[j] = ep[lane * 2 + 1];
        }
        float s[8];
        #pragma unroll
        for (int j = 0; j < 8; j++) {
            s[j] = v0[j].x * xv0.x + v0[j].y * xv0.y + v0[j].z * xv0.z + v0[j].w * xv0.w
                 + v1[j].x * xv1.x + v1[j].y * xv1.y + v1[j].z * xv1.z + v1[j].w * xv1.w;
        }
        #pragma unroll
        for (int o = 16; o > 0; o >>= 1) {
            #pragma unroll
            for (int j = 0; j < 8; j++) s[j] += __shfl_xor_sync(0xFFFFFFFFu, s[j], o);
        }
        if (lane < 8) {
            int a = a0 + lane;
            int ir = r_space[base + a];
            float m = mask[base + a];
            sc[a] = s[lane] + rp[ir] - (1.0f - m) * HUGEV;
        }
    }
    __syncthreads();

    float s = sc[t];

    float mx = s;
    #pragma unroll
    for (int o = 16; o > 0; o >>= 1) mx = fmaxf(mx, __shfl_xor_sync(0xFFFFFFFFu, mx, o));
    if (lane == 0) red[warp] = mx;
    __syncthreads();
    if (t < 8) {
        float v = red[t];
        #pragma unroll
        for (int o = 4; o > 0; o >>= 1) v = fmaxf(v, __shfl_xor_sync(0xFFu, v, o));
        if (t == 0) red[0] = v;
    }
    __syncthreads();
    mx = red[0];

    float ex = expf(s - mx);

    float sm = ex;
    #pragma unroll
    for (int o = 16; o > 0; o >>= 1) sm += __shfl_xor_sync(0xFFFFFFFFu, sm, o);
    __syncthreads();
    if (lane == 0) red[warp] = sm;
    __syncthreads();
    if (t < 8) {
        float v = red[t];
        #pragma unroll
        for (int o = 4; o > 0; o >>= 1) v += __shfl_xor_sync(0xFFu, v, o);
        if (t == 0) red[0] = v;
    }
    __syncthreads();
    float total = red[0];

    float p = ex / total;
    dist[(size_t)b * AN + t] = p;

    float term = p * logf(fmaxf(p, 1e-20f));
    float es = term;
    #pragma unroll
    for (int o = 16; o > 0; o >>= 1) es += __shfl_xor_sync(0xFFFFFFFFu, es, o);
    __syncthreads();
    if (lane == 0) red[warp] = es;
    __syncthreads();
    if (t < 8) {
        float v = red[t];
        #pragma unroll
        for (int o = 4; o > 0; o >>= 1) v += __shfl_xor_sync(0xFFu, v, o);
        if (t == 0) entropy[b] = -v;
    }
}

// ---------------------------------------------------------------------------
extern "C" void kernel_launch(void* const* d_in, const int* in_sizes, int n_in,
                              void* d_out, int out_size)
{
    const int*   e        = (const int*)  d_in[0];
    const int*   q        = (const int*)  d_in[1];
    const float* hstate   = (const float*)d_in[2];
    const int*   r_space  = (const int*)  d_in[3];
    const int*   e_space  = (const int*)  d_in[4];
    const float* amask    = (const float*)d_in[5];
    const float* ent_emb  = (const float*)d_in[6];
    const float* rel_emb  = (const float*)d_in[7];
    const float* W1       = (const float*)d_in[8];
    const float* b1       = (const float*)d_in[9];
    const float* W2       = (const float*)d_in[10];
    const float* b2       = (const float*)d_in[11];

    float* dist    = (float*)d_out;
    float* entropy = (float*)d_out + (size_t)BB * AN;

    k_prep<<<(U_TOT + 255) / 256, 256>>>(e, q, hstate, ent_emb, rel_emb, W1, W2);
    k_br<<<(NRR + 7) / 8, 256>>>(b2, rel_emb);

    dim3 gw((NRR + 63) / 64, AD / 64);          // (7, 8) = 56
    k_wr<<<gw, 256>>>();

    dim3 g1(AD / 64, BB / 64, 2);               // (8, 16, 2) = 256
    k_gemm1<<<g1, 256>>>();

    k_comb1<<<BB * AD / 4 / 256, 256>>>(b1);    // 512 blocks

    dim3 g2((NF2 + 63) / 64, BB / 64, 2);       // (11, 16, 2) = 352
    k_gemm2f<<<g2, 256>>>();

    k_scores<<<BB, 256>>>(r_space, e_space, amask, ent_emb, b2, dist, entropy);
}